// round 8
// baseline (speedup 1.0000x reference)
#include <cuda_runtime.h>
#include <cstdint>

// x: [64, 3, 512, 512] float32
// keep_mask: [64, 32, 32] -> widened to 32-bit words (nonzero == keep)
// out = x * upsample16(keep_mask)
//
// R8: R4 body (32B/group, one mask word, predicated read elision, streaming
// hints) inside a persistent grid-stride loop: 1184 resident CTAs, no wave
// transitions, no tail. Iterations pipeline via scoreboard (no register
// batching -- that regressed in R5/R7).

static constexpr int B = 64;
static constexpr int C = 3;
static constexpr int H = 512;
static constexpr int W = 512;
static constexpr long long N  = (long long)B * C * H * W;  // 50,331,648 floats
static constexpr long long N8 = N / 8;                     // 6,291,456 groups of 8

static constexpr int THREADS = 256;
static constexpr int BLOCKS  = 148 * 8;                    // 1184 resident CTAs

__global__ void __launch_bounds__(THREADS) patchmask_kernel(
    const float4* __restrict__ x4,
    const uint32_t* __restrict__ keep,
    float4* __restrict__ out4)
{
    const long long stride = (long long)gridDim.x * blockDim.x;
    const float4 z = make_float4(0.f, 0.f, 0.f, 0.f);

    for (long long i = (long long)blockIdx.x * blockDim.x + threadIdx.x;
         i < N8; i += stride)
    {
        long long base = i << 3;               // float index of first of 8
        int w  = (int)(base & (W - 1));        // W = 512
        int h  = (int)((base >> 9) & (H - 1)); // H = 512
        int b  = (int)(base >> 18) / C;        // C = 3

        int midx = b * 1024 + ((h >> 4) << 5) + (w >> 4);
        bool m = __ldg(keep + midx) != 0u;

        long long j = i << 1;                  // float4 index
        float4 v0 = m ? __ldcs(x4 + j)     : z;
        float4 v1 = m ? __ldcs(x4 + j + 1) : z;
        __stcs(out4 + j,     v0);
        __stcs(out4 + j + 1, v1);
    }
}

extern "C" void kernel_launch(void* const* d_in, const int* in_sizes, int n_in,
                              void* d_out, int out_size)
{
    const float4*   x4   = (const float4*)d_in[0];
    const uint32_t* keep = (const uint32_t*)d_in[1];
    float4*         out4 = (float4*)d_out;

    patchmask_kernel<<<BLOCKS, THREADS>>>(x4, keep, out4);
}

// round 9
// speedup vs baseline: 1.1001x; 1.1001x over previous
#include <cuda_runtime.h>
#include <cstdint>

// x: [64, 3, 512, 512] float32
// keep_mask: [64, 32, 32] -> widened to 32-bit words (nonzero == keep)
// out = x * upsample16(keep_mask)
//
// R9: R3's perfectly-coalesced map (ONE float4 per thread -> per-instruction
// warp footprint = 4 cache lines, minimal L1tex wavefronts) combined with
// predicated read elision (masked patches: no x read, ~32MB DRAM saved) and
// streaming cache hints. Insight from R3..R8: L1%/DRAM% track per-instruction
// line scatter; all multi-float4-per-thread layouts scattered lanes.

static constexpr int B = 64;
static constexpr int C = 3;
static constexpr int H = 512;
static constexpr int W = 512;
static constexpr long long N  = (long long)B * C * H * W;  // 50,331,648 floats
static constexpr long long N4 = N / 4;                     // 12,582,912 float4s

__global__ void __launch_bounds__(256) patchmask_kernel(
    const float4* __restrict__ x4,
    const uint32_t* __restrict__ keep,
    float4* __restrict__ out4)
{
    long long i = (long long)blockIdx.x * blockDim.x + threadIdx.x;
    if (i >= N4) return;

    long long base = i << 2;               // float index of first of 4 elems
    int w  = (int)(base & (W - 1));        // W = 512
    int h  = (int)((base >> 9) & (H - 1)); // H = 512
    int b  = (int)(base >> 18) / C;        // C = 3

    int midx = b * 1024 + ((h >> 4) << 5) + (w >> 4);
    bool m = __ldg(keep + midx) != 0u;

    // Branchless predicated load: masked lanes request no sectors.
    const float4 z = make_float4(0.f, 0.f, 0.f, 0.f);
    float4 v = m ? __ldcs(x4 + i) : z;

    __stcs(out4 + i, v);
}

extern "C" void kernel_launch(void* const* d_in, const int* in_sizes, int n_in,
                              void* d_out, int out_size)
{
    const float4*   x4   = (const float4*)d_in[0];
    const uint32_t* keep = (const uint32_t*)d_in[1];
    float4*         out4 = (float4*)d_out;

    const int threads = 256;
    const long long blocks = (N4 + threads - 1) / threads;  // 49152
    patchmask_kernel<<<(unsigned)blocks, threads>>>(x4, keep, out4);
}

// round 10
// speedup vs baseline: 1.2192x; 1.1082x over previous
#include <cuda_runtime.h>
#include <cstdint>

// x: [64, 3, 512, 512] float32
// keep_mask: [64, 32, 32] -> widened to 32-bit words (nonzero == keep)
// out = x * upsample16(keep_mask)
//
// R10: two WARP-STRIDED float4s per thread (i0 = blk*512+tid, i1 = i0+256).
//  - every LDG/STG instruction: 32 lanes on consecutive float4s -> 4-line
//    footprint (R3-grade coalescing, low L1tex wavefront pressure)
//  - per thread: 2 independent mask loads + 2 independently-predicated data
//    loads -> elision kept WITHOUT the single-chain serialization of R9
//  - slots 4KB apart -> tight locality (unlike R7's 1.5M-stride slots)

static constexpr int B = 64;
static constexpr int C = 3;
static constexpr int H = 512;
static constexpr int W = 512;
static constexpr long long N  = (long long)B * C * H * W;  // 50,331,648 floats
static constexpr long long N4 = N / 4;                     // 12,582,912 float4s

static constexpr int THREADS = 256;
// each block covers 2*THREADS consecutive float4s
static constexpr long long BLOCKS = N4 / (2 * THREADS);    // 24576, exact

__device__ __forceinline__ bool mask_at(const uint32_t* __restrict__ keep,
                                        long long i /*float4 idx*/)
{
    long long base = i << 2;               // float index
    int w  = (int)(base & (W - 1));        // W = 512
    int h  = (int)((base >> 9) & (H - 1)); // H = 512
    int b  = (int)(base >> 18) / C;        // C = 3
    return __ldg(keep + b * 1024 + ((h >> 4) << 5) + (w >> 4)) != 0u;
}

__global__ void __launch_bounds__(THREADS) patchmask_kernel(
    const float4* __restrict__ x4,
    const uint32_t* __restrict__ keep,
    float4* __restrict__ out4)
{
    long long i0 = (long long)blockIdx.x * (2 * THREADS) + threadIdx.x;
    long long i1 = i0 + THREADS;

    // two independent mask chains
    bool m0 = mask_at(keep, i0);
    bool m1 = mask_at(keep, i1);

    const float4 z = make_float4(0.f, 0.f, 0.f, 0.f);

    // two independently-predicated, perfectly-coalesced data loads
    float4 v0 = m0 ? __ldcs(x4 + i0) : z;
    float4 v1 = m1 ? __ldcs(x4 + i1) : z;

    __stcs(out4 + i0, v0);
    __stcs(out4 + i1, v1);
}

extern "C" void kernel_launch(void* const* d_in, const int* in_sizes, int n_in,
                              void* d_out, int out_size)
{
    const float4*   x4   = (const float4*)d_in[0];
    const uint32_t* keep = (const uint32_t*)d_in[1];
    float4*         out4 = (float4*)d_out;

    patchmask_kernel<<<(unsigned)BLOCKS, THREADS>>>(x4, keep, out4);
}